// round 3
// baseline (speedup 1.0000x reference)
#include <cuda_runtime.h>

// GIoU loss mean over N=4,000,000 box pairs. Single fused kernel:
// HBM-bound streaming + last-block-done deterministic reduction.

#define NBLOCKS 1184   // 8 waves of 148 SMs
#define NTHREADS 256

__device__ float g_partials[NBLOCKS];
__device__ unsigned int g_count;   // zero-init at load; last block resets -> replay-safe

__device__ __forceinline__ float giou_term(float4 p, float4 t) {
    float area_p = (p.z - p.x) * (p.w - p.y);
    float area_t = (t.z - t.x) * (t.w - t.y);

    float iw = fmaxf(fminf(p.z, t.z) - fmaxf(p.x, t.x), 0.0f);
    float ih = fmaxf(fminf(p.w, t.w) - fmaxf(p.y, t.y), 0.0f);
    float inter = iw * ih;
    float uni   = area_p + area_t - inter;
    float iou   = inter / uni;

    float cw = fmaxf(p.z, t.z) - fminf(p.x, t.x);
    float ch = fmaxf(p.w, t.w) - fminf(p.y, t.y);
    float area_c = cw * ch;

    float giou = iou - (area_c - uni) / area_c;
    return 1.0f - giou;
}

__global__ __launch_bounds__(NTHREADS)
void giou_fused_kernel(const float4* __restrict__ pred,
                       const float4* __restrict__ tgt,
                       float* __restrict__ out,
                       int n, float inv_n) {
    const int stride = gridDim.x * blockDim.x;
    int i = blockIdx.x * blockDim.x + threadIdx.x;

    float acc = 0.0f;

    // Unrolled-by-4: 8 independent LDG.128 front-batched per iteration (high MLP).
    for (; i + 3 * stride < n; i += 4 * stride) {
        float4 p0 = __ldg(&pred[i]);
        float4 p1 = __ldg(&pred[i +     stride]);
        float4 p2 = __ldg(&pred[i + 2 * stride]);
        float4 p3 = __ldg(&pred[i + 3 * stride]);
        float4 t0 = __ldg(&tgt[i]);
        float4 t1 = __ldg(&tgt[i +     stride]);
        float4 t2 = __ldg(&tgt[i + 2 * stride]);
        float4 t3 = __ldg(&tgt[i + 3 * stride]);
        acc += giou_term(p0, t0);
        acc += giou_term(p1, t1);
        acc += giou_term(p2, t2);
        acc += giou_term(p3, t3);
    }
    for (; i < n; i += stride)
        acc += giou_term(__ldg(&pred[i]), __ldg(&tgt[i]));

    // Intra-block reduction (fixed order -> deterministic)
    #pragma unroll
    for (int o = 16; o > 0; o >>= 1)
        acc += __shfl_xor_sync(0xffffffffu, acc, o);

    __shared__ float s[NTHREADS / 32];
    if ((threadIdx.x & 31) == 0) s[threadIdx.x >> 5] = acc;
    __syncthreads();

    __shared__ bool is_last;
    if (threadIdx.x == 0) {
        float v = 0.0f;
        #pragma unroll
        for (int w = 0; w < NTHREADS / 32; w++) v += s[w];
        g_partials[blockIdx.x] = v;
        __threadfence();
        unsigned int prev = atomicAdd(&g_count, 1u);
        is_last = (prev == (unsigned int)(gridDim.x - 1));
    }
    __syncthreads();

    if (!is_last) return;

    // Last block: reduce all partials (L2-hot). Fixed per-thread strided
    // order + fixed shuffle tree -> deterministic across replays.
    float v = 0.0f;
    for (int b = threadIdx.x; b < NBLOCKS; b += NTHREADS)
        v += g_partials[b];

    #pragma unroll
    for (int o = 16; o > 0; o >>= 1)
        v += __shfl_xor_sync(0xffffffffu, v, o);

    __shared__ float s2[NTHREADS / 32];
    if ((threadIdx.x & 31) == 0) s2[threadIdx.x >> 5] = v;
    __syncthreads();

    if (threadIdx.x == 0) {
        float r = 0.0f;
        #pragma unroll
        for (int w = 0; w < NTHREADS / 32; w++) r += s2[w];
        *out = r * inv_n;
        g_count = 0;   // reset for next graph replay (deterministic)
    }
}

extern "C" void kernel_launch(void* const* d_in, const int* in_sizes, int n_in,
                              void* d_out, int out_size) {
    const float4* pred = (const float4*)d_in[0];
    const float4* tgt  = (const float4*)d_in[1];
    float* out = (float*)d_out;

    const int n = in_sizes[0] / 4;   // floats -> boxes

    giou_fused_kernel<<<NBLOCKS, NTHREADS>>>(pred, tgt, out, n, 1.0f / (float)n);
}

// round 4
// speedup vs baseline: 1.0955x; 1.0955x over previous
#include <cuda_runtime.h>

// GIoU loss mean over N=4,000,000 box pairs. Single fused kernel.
// Simple grid-stride loop (MLP_p1 kept LOW — high front-batched LDG count
// causes cross-CTA L1tex-queue spread on B300) + last-block-done reduction.

#define NBLOCKS 1184   // 8 waves of 148 SMs
#define NTHREADS 256

__device__ float g_partials[NBLOCKS];
__device__ unsigned int g_count;   // zero at load; last block resets -> replay-safe

__global__ __launch_bounds__(NTHREADS)
void giou_fused_kernel(const float4* __restrict__ pred,
                       const float4* __restrict__ tgt,
                       float* __restrict__ out,
                       int n, float inv_n) {
    const int stride = gridDim.x * blockDim.x;
    float acc = 0.0f;

    for (int i = blockIdx.x * blockDim.x + threadIdx.x; i < n; i += stride) {
        float4 p = __ldg(&pred[i]);   // (x1, y1, x2, y2)
        float4 t = __ldg(&tgt[i]);

        float area_p = (p.z - p.x) * (p.w - p.y);
        float area_t = (t.z - t.x) * (t.w - t.y);

        float iw = fmaxf(fminf(p.z, t.z) - fmaxf(p.x, t.x), 0.0f);
        float ih = fmaxf(fminf(p.w, t.w) - fmaxf(p.y, t.y), 0.0f);
        float inter = iw * ih;
        float uni   = area_p + area_t - inter;
        float iou   = inter / uni;

        float cw = fmaxf(p.z, t.z) - fminf(p.x, t.x);
        float ch = fmaxf(p.w, t.w) - fminf(p.y, t.y);
        float area_c = cw * ch;

        float giou = iou - (area_c - uni) / area_c;
        acc += 1.0f - giou;
    }

    // Intra-block reduction (fixed order -> deterministic)
    #pragma unroll
    for (int o = 16; o > 0; o >>= 1)
        acc += __shfl_xor_sync(0xffffffffu, acc, o);

    __shared__ float s[NTHREADS / 32];
    if ((threadIdx.x & 31) == 0) s[threadIdx.x >> 5] = acc;
    __syncthreads();

    __shared__ bool is_last;
    if (threadIdx.x == 0) {
        float v = 0.0f;
        #pragma unroll
        for (int w = 0; w < NTHREADS / 32; w++) v += s[w];
        g_partials[blockIdx.x] = v;
        __threadfence();
        unsigned int prev = atomicAdd(&g_count, 1u);
        is_last = (prev == (unsigned int)(gridDim.x - 1));
    }
    __syncthreads();

    if (!is_last) return;

    // Last block: reduce all 1184 partials (L2-hot). Fixed per-thread strided
    // order + fixed tree -> deterministic across replays.
    float v = 0.0f;
    for (int b = threadIdx.x; b < NBLOCKS; b += NTHREADS)
        v += g_partials[b];

    #pragma unroll
    for (int o = 16; o > 0; o >>= 1)
        v += __shfl_xor_sync(0xffffffffu, v, o);

    __shared__ float s2[NTHREADS / 32];
    if ((threadIdx.x & 31) == 0) s2[threadIdx.x >> 5] = v;
    __syncthreads();

    if (threadIdx.x == 0) {
        float r = 0.0f;
        #pragma unroll
        for (int w = 0; w < NTHREADS / 32; w++) r += s2[w];
        *out = r * inv_n;
        g_count = 0;   // reset for next replay
    }
}

extern "C" void kernel_launch(void* const* d_in, const int* in_sizes, int n_in,
                              void* d_out, int out_size) {
    const float4* pred = (const float4*)d_in[0];
    const float4* tgt  = (const float4*)d_in[1];
    float* out = (float*)d_out;

    const int n = in_sizes[0] / 4;   // floats -> boxes

    giou_fused_kernel<<<NBLOCKS, NTHREADS>>>(pred, tgt, out, n, 1.0f / (float)n);
}